// round 1
// baseline (speedup 1.0000x reference)
#include <cuda_runtime.h>

// convection_vectors: (N_NODES, 3) float32      -> d_in[0]
// mesh_elements:      (E, 4)       int32        -> d_in[1]
// inv_matrices:       (E, 4, 4)    float32      -> d_in[2]
// out:                (E, 4, 3)    float32      -> d_out
//
// out[e,i,c] = sum_j inv[e,i,j] * conv[mesh[e,j], c]

__global__ void __launch_bounds__(256)
fem_gather_matmul_kernel(const float* __restrict__ conv,
                         const int4*  __restrict__ elems,
                         const float4* __restrict__ inv,
                         float4* __restrict__ out,
                         int E)
{
    int e = blockIdx.x * blockDim.x + threadIdx.x;
    if (e >= E) return;

    // 4 vertex indices, 16B coalesced
    int4 idx = __ldg(&elems[e]);

    // Gather 4 vertices x 3 components from the L2-resident table.
    // 12 independent loads -> high MLP to hide L2 latency.
    long b0 = (long)idx.x * 3;
    long b1 = (long)idx.y * 3;
    long b2 = (long)idx.z * 3;
    long b3 = (long)idx.w * 3;

    float g00 = __ldg(conv + b0 + 0), g01 = __ldg(conv + b0 + 1), g02 = __ldg(conv + b0 + 2);
    float g10 = __ldg(conv + b1 + 0), g11 = __ldg(conv + b1 + 1), g12 = __ldg(conv + b1 + 2);
    float g20 = __ldg(conv + b2 + 0), g21 = __ldg(conv + b2 + 1), g22 = __ldg(conv + b2 + 2);
    float g30 = __ldg(conv + b3 + 0), g31 = __ldg(conv + b3 + 1), g32 = __ldg(conv + b3 + 2);

    // 64B contiguous inverse matrix: rows m0..m3 (each a float4 = one matrix row)
    const float4* invE = inv + (long)e * 4;
    float4 m0 = __ldg(invE + 0);
    float4 m1 = __ldg(invE + 1);
    float4 m2 = __ldg(invE + 2);
    float4 m3 = __ldg(invE + 3);

    // r_i[c] = m_i.x*g0c + m_i.y*g1c + m_i.z*g2c + m_i.w*g3c
    float r00 = fmaf(m0.x, g00, fmaf(m0.y, g10, fmaf(m0.z, g20, m0.w * g30)));
    float r01 = fmaf(m0.x, g01, fmaf(m0.y, g11, fmaf(m0.z, g21, m0.w * g31)));
    float r02 = fmaf(m0.x, g02, fmaf(m0.y, g12, fmaf(m0.z, g22, m0.w * g32)));

    float r10 = fmaf(m1.x, g00, fmaf(m1.y, g10, fmaf(m1.z, g20, m1.w * g30)));
    float r11 = fmaf(m1.x, g01, fmaf(m1.y, g11, fmaf(m1.z, g21, m1.w * g31)));
    float r12 = fmaf(m1.x, g02, fmaf(m1.y, g12, fmaf(m1.z, g22, m1.w * g32)));

    float r20 = fmaf(m2.x, g00, fmaf(m2.y, g10, fmaf(m2.z, g20, m2.w * g30)));
    float r21 = fmaf(m2.x, g01, fmaf(m2.y, g11, fmaf(m2.z, g21, m2.w * g31)));
    float r22 = fmaf(m2.x, g02, fmaf(m2.y, g12, fmaf(m2.z, g22, m2.w * g32)));

    float r30 = fmaf(m3.x, g00, fmaf(m3.y, g10, fmaf(m3.z, g20, m3.w * g30)));
    float r31 = fmaf(m3.x, g01, fmaf(m3.y, g11, fmaf(m3.z, g21, m3.w * g31)));
    float r32 = fmaf(m3.x, g02, fmaf(m3.y, g12, fmaf(m3.z, g22, m3.w * g32)));

    // 12 floats = 48B per element, packed as 3 x float4 (16B-aligned: e*48B)
    float4* outE = out + (long)e * 3;
    outE[0] = make_float4(r00, r01, r02, r10);
    outE[1] = make_float4(r11, r12, r20, r21);
    outE[2] = make_float4(r22, r30, r31, r32);
}

extern "C" void kernel_launch(void* const* d_in, const int* in_sizes, int n_in,
                              void* d_out, int out_size)
{
    const float* conv  = (const float*)d_in[0];
    const int4*  elems = (const int4*)d_in[1];
    const float4* inv  = (const float4*)d_in[2];
    float4* out = (float4*)d_out;

    int E = in_sizes[1] / 4;   // mesh_elements has E*4 int32 entries

    int block = 256;
    int grid = (E + block - 1) / block;
    fem_gather_matmul_kernel<<<grid, block>>>(conv, elems, inv, out, E);
}

// round 2
// speedup vs baseline: 1.2415x; 1.2415x over previous
#include <cuda_runtime.h>

// convection_vectors: (N_NODES, 3) float32      -> d_in[0]
// mesh_elements:      (E, 4)       int32        -> d_in[1]
// inv_matrices:       (E, 4, 4)    float32      -> d_in[2]
// out:                (E, 4, 3)    float32      -> d_out
//
// out[e,i,c] = sum_j inv[e,i,j] * conv[mesh[e,j], c]

#define MAX_NODES 400000

// Padded gather table: (N, 4) float4 so each vertex is one aligned 16B load.
// 6.4 MB -> L2-resident. __device__ global (no allocation allowed).
__device__ float4 g_conv4[MAX_NODES];

__global__ void __launch_bounds__(256)
pad_conv_kernel(const float* __restrict__ conv, int n)
{
    int i = blockIdx.x * blockDim.x + threadIdx.x;
    if (i >= n) return;
    long b = (long)i * 3;
    g_conv4[i] = make_float4(conv[b], conv[b + 1], conv[b + 2], 0.0f);
}

// One thread per (element, row): t = e*4 + i. 8M threads.
//  - inv row:   float4 at index t          -> perfectly coalesced
//  - indices:   int4 elems[e], 4 lanes share -> 1 wavefront/warp (broadcast)
//  - gathers:   4x float4 from L2 table, lanes of same element coalesce
//  - output:    3 scalar floats at t*3     -> warp spans 384B contiguous
__global__ void __launch_bounds__(256)
fem_row_kernel(const int4*   __restrict__ elems,
               const float4* __restrict__ inv,
               float*        __restrict__ out,
               int total_rows)   // 4*E
{
    int t = blockIdx.x * blockDim.x + threadIdx.x;
    if (t >= total_rows) return;

    int e = t >> 2;

    int4 idx = __ldg(&elems[e]);

    // This thread's matrix row (element e, row i)
    float4 m = __ldg(&inv[t]);

    // Gather the 4 vertices' convection vectors (padded float4)
    float4 v0 = g_conv4[idx.x];
    float4 v1 = g_conv4[idx.y];
    float4 v2 = g_conv4[idx.z];
    float4 v3 = g_conv4[idx.w];

    float r0 = fmaf(m.x, v0.x, fmaf(m.y, v1.x, fmaf(m.z, v2.x, m.w * v3.x)));
    float r1 = fmaf(m.x, v0.y, fmaf(m.y, v1.y, fmaf(m.z, v2.y, m.w * v3.y)));
    float r2 = fmaf(m.x, v0.z, fmaf(m.y, v1.z, fmaf(m.z, v2.z, m.w * v3.z)));

    float* o = out + (long)t * 3;
    o[0] = r0;
    o[1] = r1;
    o[2] = r2;
}

extern "C" void kernel_launch(void* const* d_in, const int* in_sizes, int n_in,
                              void* d_out, int out_size)
{
    const float* conv  = (const float*)d_in[0];
    const int4*  elems = (const int4*)d_in[1];
    const float4* inv  = (const float4*)d_in[2];
    float* out = (float*)d_out;

    int n_nodes = in_sizes[0] / 3;
    int E = in_sizes[1] / 4;
    int total_rows = 4 * E;

    int block = 256;
    pad_conv_kernel<<<(n_nodes + block - 1) / block, block>>>(conv, n_nodes);
    fem_row_kernel<<<(total_rows + block - 1) / block, block>>>(elems, inv, out, total_rows);
}